// round 2
// baseline (speedup 1.0000x reference)
#include <cuda_runtime.h>
#include <cstdint>
#include <cstddef>

// ----------------------------------------------------------------------------
// ForecastNetSimple: persistent-kernel seq2seq LSTM.
//   B=128, T=512, I=8, H=512, W=96.
//   128 CTAs, each owns 4 H-columns (x 4 gates = 16 gate rows of Whh).
//   Weights resident in smem; h ping-pongs through L2 (g_h[2]); c stays in smem.
//   One custom grid barrier per step (two per decoder step).
// ----------------------------------------------------------------------------

#define NCTA   128
#define NTHR   256
#define T_ENC  512
#define W_DEC  96
#define HID    512
#define BATCH  128
#define KC     64      // k-chunk staged per double-buffer slot
#define KPAD   68      // padded smem row (2-way conflict max)
#define NCHUNK 8       // 512 / 64

__device__ float    g_h[2][BATCH][HID];
__device__ float    g_pred[BATCH];
__device__ unsigned g_bar;

__device__ __forceinline__ float sigf(float x)      { return 1.f / (1.f + __expf(-x)); }
__device__ __forceinline__ float tanh_fast(float x) { return 1.f - 2.f / (1.f + __expf(2.f * x)); }

__device__ __forceinline__ float ldcg(const float* p) {
    float v; asm volatile("ld.global.cg.f32 %0, [%1];" : "=f"(v) : "l"(p)); return v;
}
__device__ __forceinline__ void stcg(float* p, float v) {
    asm volatile("st.global.cg.f32 [%0], %1;" :: "l"(p), "f"(v));
}
__device__ __forceinline__ void cp16(uint32_t dst_smem, const float* src) {
    asm volatile("cp.async.cg.shared.global [%0], [%1], 16;" :: "r"(dst_smem), "l"(src));
}
__device__ __forceinline__ void cp_commit() { asm volatile("cp.async.commit_group;"); }
template <int N> __device__ __forceinline__ void cp_wait() {
    asm volatile("cp.async.wait_group %0;" :: "n"(N));
}

// Grid-wide barrier: monotonically increasing counter, reset by init kernel.
__device__ __forceinline__ void gridbar(unsigned& target) {
    __syncthreads();
    __threadfence();                       // all my st.cg h-writes visible at L2
    if (threadIdx.x == 0) {
        target += NCTA;
        atomicAdd(&g_bar, 1u);
        for (;;) {
            unsigned cur;
            asm volatile("ld.global.cg.u32 %0, [%1];" : "=r"(cur) : "l"(&g_bar));
            if (cur >= target) break;
            __nanosleep(32);
        }
    }
    __syncthreads();
}

// Stage h[0:128][ck*64 .. ck*64+64) into smem buffer (L1-bypassing async copy).
__device__ __forceinline__ void stage_chunk(float* hsm_buf, const float* hsrc,
                                            int ck, int tid) {
    uint32_t base = (uint32_t)__cvta_generic_to_shared(hsm_buf);
    const float* g0 = hsrc + ck * KC;
    #pragma unroll
    for (int n = 0; n < 8; ++n) {
        int idx = tid + n * NTHR;          // 2048 = 128 rows x 16 float4
        int b   = idx >> 4;
        int j   = (idx & 15) << 2;
        cp16(base + (uint32_t)(b * KPAD + j) * 4u, g0 + (size_t)b * HID + j);
    }
}

// Per-step GEMM: acc[bi*4+g] = sum_k h[b0+bi][k] * Whh[g*H + cta*4 + rg][k]
// Wsm layout: [k][16] with r_local = rg*4 + g  (so each lane's float4 = 4 gates
// of its owned column).
__device__ __forceinline__ void gemm_step(float acc[8], const float* hglob,
                                          const float* Wsm, float* hsm,
                                          int b0, int rg, int tid) {
    #pragma unroll
    for (int i = 0; i < 8; ++i) acc[i] = 0.f;

    stage_chunk(hsm, hglob, 0, tid);
    cp_commit();

    for (int ck = 0; ck < NCHUNK; ++ck) {
        if (ck + 1 < NCHUNK) {
            stage_chunk(hsm + ((ck + 1) & 1) * (BATCH * KPAD), hglob, ck + 1, tid);
            cp_commit();
            cp_wait<1>();
        } else {
            cp_wait<0>();
        }
        __syncthreads();

        const float*  hb0 = hsm + (ck & 1) * (BATCH * KPAD) + b0 * KPAD;
        const float4* Wv  = (const float4*)(Wsm + ck * KC * 16) + rg;

        #pragma unroll
        for (int kk = 0; kk < 16; ++kk) {
            float4 h0 = *(const float4*)(hb0 + kk * 4);
            float4 h1 = *(const float4*)(hb0 + KPAD + kk * 4);
            float4 w0 = Wv[(kk * 4 + 0) * 4];
            float4 w1 = Wv[(kk * 4 + 1) * 4];
            float4 w2 = Wv[(kk * 4 + 2) * 4];
            float4 w3 = Wv[(kk * 4 + 3) * 4];

            acc[0] = fmaf(h0.x, w0.x, acc[0]); acc[0] = fmaf(h0.y, w1.x, acc[0]);
            acc[0] = fmaf(h0.z, w2.x, acc[0]); acc[0] = fmaf(h0.w, w3.x, acc[0]);
            acc[1] = fmaf(h0.x, w0.y, acc[1]); acc[1] = fmaf(h0.y, w1.y, acc[1]);
            acc[1] = fmaf(h0.z, w2.y, acc[1]); acc[1] = fmaf(h0.w, w3.y, acc[1]);
            acc[2] = fmaf(h0.x, w0.z, acc[2]); acc[2] = fmaf(h0.y, w1.z, acc[2]);
            acc[2] = fmaf(h0.z, w2.z, acc[2]); acc[2] = fmaf(h0.w, w3.z, acc[2]);
            acc[3] = fmaf(h0.x, w0.w, acc[3]); acc[3] = fmaf(h0.y, w1.w, acc[3]);
            acc[3] = fmaf(h0.z, w2.w, acc[3]); acc[3] = fmaf(h0.w, w3.w, acc[3]);

            acc[4] = fmaf(h1.x, w0.x, acc[4]); acc[4] = fmaf(h1.y, w1.x, acc[4]);
            acc[4] = fmaf(h1.z, w2.x, acc[4]); acc[4] = fmaf(h1.w, w3.x, acc[4]);
            acc[5] = fmaf(h1.x, w0.y, acc[5]); acc[5] = fmaf(h1.y, w1.y, acc[5]);
            acc[5] = fmaf(h1.z, w2.y, acc[5]); acc[5] = fmaf(h1.w, w3.y, acc[5]);
            acc[6] = fmaf(h1.x, w0.z, acc[6]); acc[6] = fmaf(h1.y, w1.z, acc[6]);
            acc[6] = fmaf(h1.z, w2.z, acc[6]); acc[6] = fmaf(h1.w, w3.z, acc[6]);
            acc[7] = fmaf(h1.x, w0.w, acc[7]); acc[7] = fmaf(h1.y, w1.w, acc[7]);
            acc[7] = fmaf(h1.z, w2.w, acc[7]); acc[7] = fmaf(h1.w, w3.w, acc[7]);
        }
        __syncthreads();
    }
}

__global__ void init_kernel() {
    size_t i = (size_t)blockIdx.x * blockDim.x + threadIdx.x;
    size_t n = 2ull * BATCH * HID;
    float* h = &g_h[0][0][0];
    for (size_t idx = i; idx < n; idx += (size_t)gridDim.x * blockDim.x) h[idx] = 0.f;
    if (i == 0) g_bar = 0u;
}

__global__ void __launch_bounds__(NTHR, 1)
fore_kernel(const float* __restrict__ src,
            const float* __restrict__ Wih_e, const float* __restrict__ Whh_e,
            const float* __restrict__ bih_e, const float* __restrict__ bhh_e,
            const float* __restrict__ Wih_d, const float* __restrict__ Whh_d,
            const float* __restrict__ bih_d, const float* __restrict__ bhh_d,
            const float* __restrict__ Wp,    const float* __restrict__ bp,
            const float* __restrict__ Wfc,   const float* __restrict__ bfc,
            float* __restrict__ out)
{
    extern __shared__ float sm[];
    float* Wsm = sm;                 // [512][16]            8192 floats
    float* hsm = Wsm + 8192;         // 2 x [128][KPAD]      17408 floats
    float* csm = hsm + 2 * BATCH * KPAD; // [128][4]         512 floats
    float* bsm = csm + 512;          // 16
    float* wxa = bsm + 16;           // encoder: Wih rows [16][8]; decoder: A[16]
    float* red = wxa + 128;          // 8

    const int tid  = threadIdx.x;
    const int cta  = blockIdx.x;
    const int warp = tid >> 5, lane = tid & 31;
    const int bg   = lane >> 2, rg = lane & 3;
    const int b0   = warp * 16 + bg * 2;
    const int col  = cta * 4 + rg;   // owned global H-column for this lane

    // ---- load encoder weights (resident for the whole encoder) ----
    for (int idx = tid; idx < 8192; idx += NTHR) {
        int k = idx >> 4, rl = idx & 15;
        int g = rl & 3, c = rl >> 2;
        int grow = g * HID + cta * 4 + c;
        Wsm[k * 16 + rl] = Whh_e[(size_t)grow * HID + k];
    }
    if (tid < 16) {
        int g = tid & 3, c = tid >> 2;
        int grow = g * HID + cta * 4 + c;
        bsm[tid] = bih_e[grow] + bhh_e[grow];
        #pragma unroll
        for (int i = 0; i < 8; ++i) wxa[tid * 8 + i] = Wih_e[grow * 8 + i];
    }
    for (int i = tid; i < 512; i += NTHR) csm[i] = 0.f;
    __syncthreads();

    unsigned target = 0;
    int p = 0;

    // ======================= encoder =======================
    for (int t = 0; t < T_ENC; ++t) {
        float acc[8];
        gemm_step(acc, &g_h[p][0][0], Wsm, hsm, b0, rg, tid);

        #pragma unroll
        for (int bi = 0; bi < 2; ++bi) {
            int b = b0 + bi;
            const float* sp = src + ((size_t)b * T_ENC + t) * 8;
            float4 sa = *(const float4*)sp;
            float4 sb = *(const float4*)(sp + 4);
            float gate[4];
            #pragma unroll
            for (int g = 0; g < 4; ++g) {
                int rl = rg * 4 + g;
                const float* wr = wxa + rl * 8;
                float xg = sa.x*wr[0] + sa.y*wr[1] + sa.z*wr[2] + sa.w*wr[3]
                         + sb.x*wr[4] + sb.y*wr[5] + sb.z*wr[6] + sb.w*wr[7];
                gate[g] = acc[bi * 4 + g] + xg + bsm[rl];
            }
            float cprev = csm[b * 4 + rg];
            float ig = sigf(gate[0]), fg = sigf(gate[1]);
            float gg = tanh_fast(gate[2]), og = sigf(gate[3]);
            float cn = fg * cprev + ig * gg;
            float hn = og * tanh_fast(cn);
            csm[b * 4 + rg] = cn;
            stcg(&g_h[p ^ 1][b][col], hn);
        }
        gridbar(target);
        p ^= 1;
    }

    // ======================= decoder prep =======================
    __syncthreads();
    for (int idx = tid; idx < 8192; idx += NTHR) {
        int k = idx >> 4, rl = idx & 15;
        int g = rl & 3, c = rl >> 2;
        int grow = g * HID + cta * 4 + c;
        Wsm[k * 16 + rl] = Whh_d[(size_t)grow * HID + k];
    }
    __syncthreads();
    if (tid < 16) {
        int g = tid & 3, c = tid >> 2;
        int grow = g * HID + cta * 4 + c;
        float A = 0.f, B0 = 0.f;
        #pragma unroll
        for (int i = 0; i < 8; ++i) {
            float wih = Wih_d[grow * 8 + i];
            A  += Wp[i] * wih;       // xp = pred*Wp + bp  folded into the row
            B0 += bp[i] * wih;
        }
        bsm[tid] = bih_d[grow] + bhh_d[grow] + B0;
        wxa[tid] = A;
    }
    __syncthreads();
    const float bfcv = bfc[0];

    // ======================= decoder =======================
    for (int w = 0; w < W_DEC; ++w) {
        float acc[8];
        gemm_step(acc, &g_h[p][0][0], Wsm, hsm, b0, rg, tid);

        #pragma unroll
        for (int bi = 0; bi < 2; ++bi) {
            int b = b0 + bi;
            float xv = (w == 0) ? __ldg(&src[((size_t)b * T_ENC + (T_ENC - 1)) * 8])
                                : ldcg(&g_pred[b]);
            float gate[4];
            #pragma unroll
            for (int g = 0; g < 4; ++g) {
                int rl = rg * 4 + g;
                gate[g] = acc[bi * 4 + g] + xv * wxa[rl] + bsm[rl];
            }
            float cprev = csm[b * 4 + rg];
            float ig = sigf(gate[0]), fg = sigf(gate[1]);
            float gg = tanh_fast(gate[2]), og = sigf(gate[3]);
            float cn = fg * cprev + ig * gg;
            float hn = og * tanh_fast(cn);
            csm[b * 4 + rg] = cn;
            stcg(&g_h[p ^ 1][b][col], hn);
        }
        gridbar(target);

        // pred for batch b == cta: sigmoid(h_new . Wfc + bfc)
        {
            const float* hrow = &g_h[p ^ 1][cta][0];
            float part = 0.f;
            for (int k = tid; k < HID; k += NTHR)
                part += ldcg(hrow + k) * __ldg(&Wfc[k]);
            #pragma unroll
            for (int off = 16; off; off >>= 1)
                part += __shfl_down_sync(0xffffffffu, part, off);
            if (lane == 0) red[warp] = part;
            __syncthreads();
            if (tid == 0) {
                float s = 0.f;
                #pragma unroll
                for (int i = 0; i < 8; ++i) s += red[i];
                float pr = sigf(s + bfcv);
                stcg(&g_pred[cta], pr);
                out[cta * W_DEC + w] = pr;
            }
        }
        gridbar(target);
        p ^= 1;
    }
}

extern "C" void kernel_launch(void* const* d_in, const int* in_sizes, int n_in,
                              void* d_out, int out_size) {
    const float* src   = (const float*)d_in[0];
    const float* Wih_e = (const float*)d_in[1];
    const float* Whh_e = (const float*)d_in[2];
    const float* bih_e = (const float*)d_in[3];
    const float* bhh_e = (const float*)d_in[4];
    const float* Wih_d = (const float*)d_in[5];
    const float* Whh_d = (const float*)d_in[6];
    const float* bih_d = (const float*)d_in[7];
    const float* bhh_d = (const float*)d_in[8];
    const float* Wp    = (const float*)d_in[9];
    const float* bp    = (const float*)d_in[10];
    const float* Wfc   = (const float*)d_in[11];
    const float* bfc   = (const float*)d_in[12];
    float* out = (float*)d_out;

    size_t smem = (size_t)(8192 + 2 * BATCH * KPAD + 512 + 16 + 128 + 8) * sizeof(float);
    cudaFuncSetAttribute(fore_kernel, cudaFuncAttributeMaxDynamicSharedMemorySize, (int)smem);

    init_kernel<<<64, 256>>>();
    fore_kernel<<<NCTA, NTHR, smem>>>(src, Wih_e, Whh_e, bih_e, bhh_e,
                                      Wih_d, Whh_d, bih_d, bhh_d,
                                      Wp, bp, Wfc, bfc, out);
}

// round 6
// speedup vs baseline: 1.5015x; 1.5015x over previous
#include <cuda_runtime.h>
#include <cuda_bf16.h>
#include <cstdint>
#include <cstddef>

// ----------------------------------------------------------------------------
// ForecastNetSimple via mma.sync (HMMA, family-portable — tcgen05 PTX is
// rejected by this pipeline's compute_103 target).
//   Per step: gates[128 x 2048] = h[128 x 512] @ W[2048 x 512]^T across 64 CTAs
//   (N=32 gate rows each). bf16 3-term split (Whi*hhi + Whi*hlo + Wlo*hhi),
//   fp32 accum in registers. h ping-pongs through L2 as bf16 hi/lo; c in regs.
// ----------------------------------------------------------------------------

#define NCTA   64
#define NTHR   128
#define T_ENC  512
#define W_DEC  96
#define HID    512
#define BATCH  128
#define NG     32        // gate rows per CTA (8 H-cols x 4 gates)
#define NCHUNK 8         // K chunks of 64

// A (h) staging: [128][72] bf16 rows (144B stride -> conflict-free ldmatrix)
#define AROW       144
#define ALO_HALF   18432              // 128*144
#define SLOT_BYTES 36864              // hi + lo
// W: [32][520] bf16 rows (1040B stride)
#define WROW       1040
#define WHI_OFF    73728              // 2 slots * 36864
#define WLO_OFF    107008             // +33280
#define CSM_OFF    140288             // f32 [128][33] = 16896 B
#define WIH_OFF    157184             // f32 [32][8]
#define BSM_OFF    158208             // f32 [32]
#define WXA_OFF    158336             // f32 [32]
#define RED_OFF    158464             // f32 [4]
#define SMEM_TOTAL 158720

__device__ __nv_bfloat16 g_hhi[2][BATCH][HID];
__device__ __nv_bfloat16 g_hlo[2][BATCH][HID];
__device__ float         g_pred[BATCH];
__device__ unsigned      g_bar;

__device__ __forceinline__ float sigf(float x)     { return 1.f / (1.f + __expf(-x)); }
__device__ __forceinline__ float tanh_acc(float x) { return 1.f - 2.f / (1.f + __expf(2.f * x)); }

__device__ __forceinline__ uint32_t smem_u32_of(const void* p) {
    uint32_t a;
    asm("{ .reg .u64 t; cvta.to.shared.u64 t, %1; cvt.u32.u64 %0, t; }" : "=r"(a) : "l"(p));
    return a;
}
__device__ __forceinline__ float ldcg(const float* p) {
    float v; asm volatile("ld.global.cg.f32 %0, [%1];" : "=f"(v) : "l"(p)); return v;
}
__device__ __forceinline__ void stcg(float* p, float v) {
    asm volatile("st.global.cg.f32 [%0], %1;" :: "l"(p), "f"(v));
}
__device__ __forceinline__ void stcg128(void* p, uint32_t a, uint32_t b, uint32_t c, uint32_t d) {
    asm volatile("st.global.cg.v4.b32 [%0], {%1,%2,%3,%4};" :: "l"(p), "r"(a), "r"(b), "r"(c), "r"(d));
}
__device__ __forceinline__ void ldcg128(const void* p, uint32_t& a, uint32_t& b, uint32_t& c, uint32_t& d) {
    asm volatile("ld.global.cg.v4.b32 {%0,%1,%2,%3}, [%4];" : "=r"(a), "=r"(b), "=r"(c), "=r"(d) : "l"(p));
}
__device__ __forceinline__ void cp16(uint32_t dst, const void* src) {
    asm volatile("cp.async.cg.shared.global [%0], [%1], 16;" :: "r"(dst), "l"(src));
}
__device__ __forceinline__ void cp_commit() { asm volatile("cp.async.commit_group;"); }
template <int N> __device__ __forceinline__ void cp_wait() {
    asm volatile("cp.async.wait_group %0;" :: "n"(N));
}
__device__ __forceinline__ void ldsm4(uint32_t& r0, uint32_t& r1, uint32_t& r2, uint32_t& r3,
                                      uint32_t addr) {
    asm volatile("ldmatrix.sync.aligned.m8n8.x4.shared.b16 {%0,%1,%2,%3}, [%4];"
                 : "=r"(r0), "=r"(r1), "=r"(r2), "=r"(r3) : "r"(addr));
}
__device__ __forceinline__ void mma16816(float* c, uint32_t a0, uint32_t a1, uint32_t a2,
                                         uint32_t a3, uint32_t b0, uint32_t b1) {
    asm volatile("mma.sync.aligned.m16n8k16.row.col.f32.bf16.bf16.f32 "
                 "{%0,%1,%2,%3}, {%4,%5,%6,%7}, {%8,%9}, {%0,%1,%2,%3};"
                 : "+f"(c[0]), "+f"(c[1]), "+f"(c[2]), "+f"(c[3])
                 : "r"(a0), "r"(a1), "r"(a2), "r"(a3), "r"(b0), "r"(b1));
}

// Grid-wide barrier (64 CTAs)
__device__ __forceinline__ void gridbar(unsigned& target) {
    __syncthreads();
    __threadfence();
    if (threadIdx.x == 0) {
        target += NCTA;
        atomicAdd(&g_bar, 1u);
        for (;;) {
            unsigned cur;
            asm volatile("ld.global.cg.u32 %0, [%1];" : "=r"(cur) : "l"(&g_bar));
            if (cur >= target) break;
            __nanosleep(32);
        }
    }
    __syncthreads();
}

// Stage one K-chunk (64 cols) of h hi+lo into a slot (padded rows, L1-bypass).
__device__ __forceinline__ void stage(uint32_t smem_b, int slot, int ck, int p, int tid) {
    uint32_t base = smem_b + (uint32_t)slot * SLOT_BYTES;
    const char* shi = (const char*)&g_hhi[p][0][ck * 64];
    const char* slo = (const char*)&g_hlo[p][0][ck * 64];
    #pragma unroll
    for (int i = 0; i < 8; ++i) {
        int idx = i * NTHR + tid;            // 1024 16B pieces
        int b = idx >> 3, j = idx & 7;
        uint32_t off = (uint32_t)(b * AROW + j * 16);
        cp16(base + off,            shi + (size_t)b * (HID * 2) + j * 16);
        cp16(base + ALO_HALF + off, slo + (size_t)b * (HID * 2) + j * 16);
    }
}

// Load W slice (32 rows x 512) as bf16 hi/lo, row-major [n][k], padded rows.
__device__ __forceinline__ void load_W(const float* __restrict__ Whh, char* sm, int cta, int tid) {
    for (int idx = tid; idx < NG * HID; idx += NTHR) {
        int n = idx >> 9, k = idx & 511;
        int c = n >> 2, g = n & 3;
        int row = g * HID + cta * 8 + c;
        float w = Whh[(size_t)row * HID + k];
        __nv_bfloat16 whi = __float2bfloat16(w);
        __nv_bfloat16 wlo = __float2bfloat16(w - __bfloat162float(whi));
        uint32_t off = (uint32_t)(n * WROW + k * 2);
        *(__nv_bfloat16*)(sm + WHI_OFF + off) = whi;
        *(__nv_bfloat16*)(sm + WLO_OFF + off) = wlo;
    }
}

__global__ void init_kernel() {
    size_t i = (size_t)blockIdx.x * blockDim.x + threadIdx.x;
    uint32_t* hh = (uint32_t*)&g_hhi[0][0][0];
    uint32_t* hl = (uint32_t*)&g_hlo[0][0][0];
    size_t n = 2ull * BATCH * HID / 2;
    for (size_t k = i; k < n; k += (size_t)gridDim.x * blockDim.x) { hh[k] = 0u; hl[k] = 0u; }
    if (i == 0) g_bar = 0u;
}

__global__ void __launch_bounds__(NTHR, 1)
fore_kernel(const float* __restrict__ src,
            const float* __restrict__ Wih_e, const float* __restrict__ Whh_e,
            const float* __restrict__ bih_e, const float* __restrict__ bhh_e,
            const float* __restrict__ Wih_d, const float* __restrict__ Whh_d,
            const float* __restrict__ bih_d, const float* __restrict__ bhh_d,
            const float* __restrict__ Wp,    const float* __restrict__ bp,
            const float* __restrict__ Wfc,   const float* __restrict__ bfc,
            float* __restrict__ out)
{
    extern __shared__ char sm[];
    const uint32_t smem_b = smem_u32_of(sm);
    float* Csm    = (float*)(sm + CSM_OFF);
    float* wih_sm = (float*)(sm + WIH_OFF);
    float* bsm    = (float*)(sm + BSM_OFF);
    float* wxa    = (float*)(sm + WXA_OFF);
    float* red    = (float*)(sm + RED_OFF);

    const int tid  = threadIdx.x;
    const int cta  = blockIdx.x;
    const int wid  = tid >> 5;
    const int lane = tid & 31;
    const int b    = tid;                // thread owns batch b in epilogue
    const int m0   = wid * 32;           // warp's M block

    // ldmatrix per-lane address components
    const uint32_t a_off   = (uint32_t)(((lane & 7) + ((lane >> 3) & 1) * 8) * AROW
                                        + ((lane >> 4) & 1) * 16);
    const uint32_t b_roff  = (uint32_t)((((lane >> 4) & 1) * 8 + (lane & 7)) * WROW
                                        + ((lane >> 3) & 1) * 16);

    // ---- encoder weights ----
    load_W(Whh_e, sm, cta, tid);
    if (tid < NG * 8) {
        int n = tid >> 3, i = tid & 7;
        int c = n >> 2, g = n & 3;
        int row = g * HID + cta * 8 + c;
        wih_sm[n * 8 + i] = Wih_e[row * 8 + i];
    }
    if (tid < NG) {
        int c = tid >> 2, g = tid & 3;
        int row = g * HID + cta * 8 + c;
        bsm[tid] = bih_e[row] + bhh_e[row];
    }
    __syncthreads();

    float cc[8];
    #pragma unroll
    for (int i = 0; i < 8; ++i) cc[i] = 0.f;

    unsigned target = 0;
    int p = 0;

    for (int step = 0; step < T_ENC + W_DEC; ++step) {
        const bool enc = (step < T_ENC);
        const int  t   = enc ? step : step - T_ENC;

        // decoder weight swap (once)
        if (step == T_ENC) {
            load_W(Whh_d, sm, cta, tid);
            __syncthreads();
            if (tid < NG) {
                int c = tid >> 2, g = tid & 3;
                int row = g * HID + cta * 8 + c;
                float A = 0.f, B0 = 0.f;
                #pragma unroll
                for (int i = 0; i < 8; ++i) {
                    float wih = Wih_d[row * 8 + i];
                    A  += Wp[i] * wih;
                    B0 += bp[i] * wih;
                }
                bsm[tid] = bih_d[row] + bhh_d[row] + B0;
                wxa[tid] = A;
            }
            __syncthreads();
        }

        // =================== step GEMM (HMMA) ===================
        float acc[2][4][4];
        #pragma unroll
        for (int i = 0; i < 2; ++i)
            #pragma unroll
            for (int j = 0; j < 4; ++j)
                #pragma unroll
                for (int q = 0; q < 4; ++q) acc[i][j][q] = 0.f;

        stage(smem_b, 0, 0, p, tid); cp_commit();

        #pragma unroll
        for (int ck = 0; ck < NCHUNK; ++ck) {
            if (ck + 1 < NCHUNK) {
                stage(smem_b, (ck + 1) & 1, ck + 1, p, tid); cp_commit();
                cp_wait<1>();
            } else {
                cp_wait<0>();
            }
            __syncthreads();                       // chunk ck resident

            const uint32_t sb  = smem_b + (uint32_t)(ck & 1) * SLOT_BYTES;
            const uint32_t ah0 = sb + (uint32_t)m0 * AROW + a_off;
            const uint32_t al0 = ah0 + ALO_HALF;
            const uint32_t wkb = smem_b + (uint32_t)(ck * 128) + b_roff;
            const uint32_t bh0 = wkb + WHI_OFF;
            const uint32_t bl0 = wkb + WLO_OFF;

            #pragma unroll
            for (int k16 = 0; k16 < 4; ++k16) {
                const uint32_t ko = (uint32_t)(k16 * 32);
                uint32_t Ah[2][4], Al[2][4], Bh[2][4], Bl[2][4];
                ldsm4(Ah[0][0], Ah[0][1], Ah[0][2], Ah[0][3], ah0 + ko);
                ldsm4(Ah[1][0], Ah[1][1], Ah[1][2], Ah[1][3], ah0 + 16 * AROW + ko);
                ldsm4(Al[0][0], Al[0][1], Al[0][2], Al[0][3], al0 + ko);
                ldsm4(Al[1][0], Al[1][1], Al[1][2], Al[1][3], al0 + 16 * AROW + ko);
                ldsm4(Bh[0][0], Bh[0][1], Bh[0][2], Bh[0][3], bh0 + ko);
                ldsm4(Bh[1][0], Bh[1][1], Bh[1][2], Bh[1][3], bh0 + 16 * WROW + ko);
                ldsm4(Bl[0][0], Bl[0][1], Bl[0][2], Bl[0][3], bl0 + ko);
                ldsm4(Bl[1][0], Bl[1][1], Bl[1][2], Bl[1][3], bl0 + 16 * WROW + ko);

                #pragma unroll
                for (int mt = 0; mt < 2; ++mt) {
                    #pragma unroll
                    for (int gN = 0; gN < 2; ++gN) {
                        // n-tiles: gN*16 + {0, 8}
                        mma16816(acc[mt][gN * 2 + 0], Ah[mt][0], Ah[mt][1], Ah[mt][2], Ah[mt][3],
                                 Bh[gN][0], Bh[gN][1]);
                        mma16816(acc[mt][gN * 2 + 1], Ah[mt][0], Ah[mt][1], Ah[mt][2], Ah[mt][3],
                                 Bh[gN][2], Bh[gN][3]);
                        mma16816(acc[mt][gN * 2 + 0], Al[mt][0], Al[mt][1], Al[mt][2], Al[mt][3],
                                 Bh[gN][0], Bh[gN][1]);
                        mma16816(acc[mt][gN * 2 + 1], Al[mt][0], Al[mt][1], Al[mt][2], Al[mt][3],
                                 Bh[gN][2], Bh[gN][3]);
                        mma16816(acc[mt][gN * 2 + 0], Ah[mt][0], Ah[mt][1], Ah[mt][2], Ah[mt][3],
                                 Bl[gN][0], Bl[gN][1]);
                        mma16816(acc[mt][gN * 2 + 1], Ah[mt][0], Ah[mt][1], Ah[mt][2], Ah[mt][3],
                                 Bl[gN][2], Bl[gN][3]);
                    }
                }
            }
            __syncthreads();                       // protect slot reuse
        }

        // dump C to smem [128][33]
        #pragma unroll
        for (int mt = 0; mt < 2; ++mt) {
            int r = m0 + mt * 16 + (lane >> 2);
            #pragma unroll
            for (int nt = 0; nt < 4; ++nt) {
                int cb = nt * 8 + (lane & 3) * 2;
                Csm[r * 33 + cb]           = acc[mt][nt][0];
                Csm[r * 33 + cb + 1]       = acc[mt][nt][1];
                Csm[(r + 8) * 33 + cb]     = acc[mt][nt][2];
                Csm[(r + 8) * 33 + cb + 1] = acc[mt][nt][3];
            }
        }
        __syncthreads();

        // =================== LSTM cell epilogue (thread = batch) ===========
        float xg8[8];
        float xv = 0.f;
        if (enc) {
            const float* sp = src + ((size_t)b * T_ENC + t) * 8;
            float4 sa = *(const float4*)sp;
            float4 sb4 = *(const float4*)(sp + 4);
            xg8[0] = sa.x; xg8[1] = sa.y; xg8[2] = sa.z; xg8[3] = sa.w;
            xg8[4] = sb4.x; xg8[5] = sb4.y; xg8[6] = sb4.z; xg8[7] = sb4.w;
        } else {
            xv = (t == 0) ? __ldg(&src[((size_t)b * T_ENC + (T_ENC - 1)) * 8])
                          : ldcg(&g_pred[b]);
        }

        uint32_t phi[4], plo[4];
        #pragma unroll
        for (int c = 0; c < 8; ++c) {
            float gate[4];
            #pragma unroll
            for (int g = 0; g < 4; ++g) {
                int n = c * 4 + g;
                float xpart;
                if (enc) {
                    const float* wr = wih_sm + n * 8;
                    xpart = xg8[0]*wr[0] + xg8[1]*wr[1] + xg8[2]*wr[2] + xg8[3]*wr[3]
                          + xg8[4]*wr[4] + xg8[5]*wr[5] + xg8[6]*wr[6] + xg8[7]*wr[7];
                } else {
                    xpart = xv * wxa[n];
                }
                gate[g] = Csm[b * 33 + n] + xpart + bsm[n];
            }
            float ig = sigf(gate[0]), fg = sigf(gate[1]);
            float gg = tanh_acc(gate[2]), og = sigf(gate[3]);
            float cn = fg * cc[c] + ig * gg;
            float hn = og * tanh_acc(cn);
            cc[c] = cn;
            __nv_bfloat16 bh = __float2bfloat16(hn);
            __nv_bfloat16 bl = __float2bfloat16(hn - __bfloat162float(bh));
            unsigned short uh = __bfloat16_as_ushort(bh), ul = __bfloat16_as_ushort(bl);
            if (c & 1) { phi[c >> 1] |= (uint32_t)uh << 16; plo[c >> 1] |= (uint32_t)ul << 16; }
            else       { phi[c >> 1]  = uh;                 plo[c >> 1]  = ul; }
        }
        stcg128(&g_hhi[p ^ 1][b][cta * 8], phi[0], phi[1], phi[2], phi[3]);
        stcg128(&g_hlo[p ^ 1][b][cta * 8], plo[0], plo[1], plo[2], plo[3]);

        gridbar(target);

        if (!enc) {
            // pred for batches 2*cta, 2*cta+1: sigmoid(h_new . Wfc + bfc)
            int half = tid >> 6;
            int bb   = 2 * cta + half;
            int k0   = (tid & 63) * 8;
            uint32_t h0,h1,h2,h3, l0,l1,l2,l3;
            ldcg128(&g_hhi[p ^ 1][bb][k0], h0, h1, h2, h3);
            ldcg128(&g_hlo[p ^ 1][bb][k0], l0, l1, l2, l3);
            float4 wa = __ldg((const float4*)(Wfc + k0));
            float4 wb4 = __ldg((const float4*)(Wfc + k0 + 4));
            uint32_t hv[4] = {h0,h1,h2,h3}, lv[4] = {l0,l1,l2,l3};
            float wf[8] = {wa.x,wa.y,wa.z,wa.w, wb4.x,wb4.y,wb4.z,wb4.w};
            float part = 0.f;
            #pragma unroll
            for (int q = 0; q < 4; ++q) {
                __nv_bfloat162 hh2 = *reinterpret_cast<__nv_bfloat162*>(&hv[q]);
                __nv_bfloat162 ll2 = *reinterpret_cast<__nv_bfloat162*>(&lv[q]);
                float e0 = __bfloat162float(hh2.x) + __bfloat162float(ll2.x);
                float e1 = __bfloat162float(hh2.y) + __bfloat162float(ll2.y);
                part = fmaf(e0, wf[q * 2], part);
                part = fmaf(e1, wf[q * 2 + 1], part);
            }
            #pragma unroll
            for (int off = 16; off; off >>= 1)
                part += __shfl_down_sync(0xffffffffu, part, off);
            if ((tid & 31) == 0) red[wid] = part;
            __syncthreads();
            if (tid == 0) {
                float bfcv = __ldg(bfc);
                float p0 = sigf(red[0] + red[1] + bfcv);
                float p1 = sigf(red[2] + red[3] + bfcv);
                stcg(&g_pred[2 * cta], p0);
                stcg(&g_pred[2 * cta + 1], p1);
                out[(2 * cta) * W_DEC + t] = p0;
                out[(2 * cta + 1) * W_DEC + t] = p1;
            }
            gridbar(target);
        }
        p ^= 1;
    }
}

extern "C" void kernel_launch(void* const* d_in, const int* in_sizes, int n_in,
                              void* d_out, int out_size) {
    const float* src   = (const float*)d_in[0];
    const float* Wih_e = (const float*)d_in[1];
    const float* Whh_e = (const float*)d_in[2];
    const float* bih_e = (const float*)d_in[3];
    const float* bhh_e = (const float*)d_in[4];
    const float* Wih_d = (const float*)d_in[5];
    const float* Whh_d = (const float*)d_in[6];
    const float* bih_d = (const float*)d_in[7];
    const float* bhh_d = (const float*)d_in[8];
    const float* Wp    = (const float*)d_in[9];
    const float* bp    = (const float*)d_in[10];
    const float* Wfc   = (const float*)d_in[11];
    const float* bfc   = (const float*)d_in[12];
    float* out = (float*)d_out;

    cudaFuncSetAttribute(fore_kernel, cudaFuncAttributeMaxDynamicSharedMemorySize, SMEM_TOTAL);

    init_kernel<<<64, 256>>>();
    fore_kernel<<<NCTA, NTHR, SMEM_TOTAL>>>(src, Wih_e, Whh_e, bih_e, bhh_e,
                                            Wih_d, Whh_d, bih_d, bhh_d,
                                            Wp, bp, Wfc, bfc, out);
}

// round 7
// speedup vs baseline: 2.5877x; 1.7233x over previous
#include <cuda_runtime.h>
#include <cuda_fp16.h>
#include <cstdint>
#include <cstddef>

// ----------------------------------------------------------------------------
// ForecastNetSimple via mma.sync fp16 split (HMMA; tcgen05 rejected by the
// compute_103 family target).
//   128 CTAs x 256 thr. Per step: gates[128 x 2048] = h @ W^T, N=16 rows/CTA.
//   fp16 3-term split with x2048-scaled lo operands:
//     accA += Whi*hhi ; accB += Whi*(hlo*2048) + (Wlo*2048)*hhi
//     gate  = accA + accB/2048            (residual ~2^-22)
//   8 warps: warps 0-3 K[0,256), warps 4-7 K[256,512); smem C reduction.
//   h ping-pongs through L2 as fp16 hi/lo; c in regs (thread=(batch,col-half)).
// ----------------------------------------------------------------------------

#define NCTA   128
#define NTHR   256
#define T_ENC  512
#define W_DEC  96
#define HID    512
#define BATCH  128
#define NG     16        // gate rows per CTA (4 H-cols x 4 gates)

#define SLOT_BYTES 32768          // hi 16KB + lo 16KB, SW128 swizzled 128B rows
#define WROW       1040           // W row stride bytes (512 fp16 + pad)
#define WHI_OFF    131072         // 4 slots * 32768
#define WLO_OFF    147712
#define CSM_OFF    164352         // f32 [128][17]
#define WIH_OFF    173056         // f32 [16][8]
#define BSM_OFF    173568         // f32 [16]
#define WXA_OFF    173632         // f32 [16]
#define RED_OFF    173696         // f32 [8]
#define WFC_OFF    173728         // f32 [512]
#define SMEM_TOTAL 175776

#define SWZ(x) ((x) ^ (((x) >> 3) & 0x70))

__device__ __half    g_hhi[2][BATCH][HID];
__device__ __half    g_hlo[2][BATCH][HID];
__device__ float     g_pred[BATCH];
__device__ unsigned  g_bar;

__device__ __forceinline__ float sigf(float x)     { return 1.f / (1.f + __expf(-x)); }
__device__ __forceinline__ float tanh_acc(float x) { return 1.f - 2.f / (1.f + __expf(2.f * x)); }

__device__ __forceinline__ uint32_t smem_u32_of(const void* p) {
    uint32_t a;
    asm("{ .reg .u64 t; cvta.to.shared.u64 t, %1; cvt.u32.u64 %0, t; }" : "=r"(a) : "l"(p));
    return a;
}
__device__ __forceinline__ float ldcg(const float* p) {
    float v; asm volatile("ld.global.cg.f32 %0, [%1];" : "=f"(v) : "l"(p)); return v;
}
__device__ __forceinline__ unsigned short ldcg_h(const __half* p) {
    unsigned short v; asm volatile("ld.global.cg.u16 %0, [%1];" : "=h"(v) : "l"(p)); return v;
}
__device__ __forceinline__ void stcg(float* p, float v) {
    asm volatile("st.global.cg.f32 [%0], %1;" :: "l"(p), "f"(v));
}
__device__ __forceinline__ void stcg32(void* p, uint32_t v) {
    asm volatile("st.global.cg.b32 [%0], %1;" :: "l"(p), "r"(v));
}
__device__ __forceinline__ void cp16(uint32_t dst, const void* src) {
    asm volatile("cp.async.cg.shared.global [%0], [%1], 16;" :: "r"(dst), "l"(src));
}
__device__ __forceinline__ void cp_commit() { asm volatile("cp.async.commit_group;"); }
template <int N> __device__ __forceinline__ void cp_wait() {
    asm volatile("cp.async.wait_group %0;" :: "n"(N));
}
__device__ __forceinline__ void ldsm4(uint32_t& r0, uint32_t& r1, uint32_t& r2, uint32_t& r3,
                                      uint32_t addr) {
    asm volatile("ldmatrix.sync.aligned.m8n8.x4.shared.b16 {%0,%1,%2,%3}, [%4];"
                 : "=r"(r0), "=r"(r1), "=r"(r2), "=r"(r3) : "r"(addr));
}
__device__ __forceinline__ void mma16816(float* c, uint32_t a0, uint32_t a1, uint32_t a2,
                                         uint32_t a3, uint32_t b0, uint32_t b1) {
    asm volatile("mma.sync.aligned.m16n8k16.row.col.f32.f16.f16.f32 "
                 "{%0,%1,%2,%3}, {%4,%5,%6,%7}, {%8,%9}, {%0,%1,%2,%3};"
                 : "+f"(c[0]), "+f"(c[1]), "+f"(c[2]), "+f"(c[3])
                 : "r"(a0), "r"(a1), "r"(a2), "r"(a3), "r"(b0), "r"(b1));
}

__device__ __forceinline__ void gridbar(unsigned& target) {
    __syncthreads();
    __threadfence();
    if (threadIdx.x == 0) {
        target += NCTA;
        atomicAdd(&g_bar, 1u);
        for (;;) {
            unsigned cur;
            asm volatile("ld.global.cg.u32 %0, [%1];" : "=r"(cur) : "l"(&g_bar));
            if (cur >= target) break;
            __nanosleep(32);
        }
    }
    __syncthreads();
}

// Stage chunk ck (64 fp16 cols of h hi+lo) into slot (SW128 swizzled rows).
__device__ __forceinline__ void stage_chunk(uint32_t smem_b, int slot, int ck, int p, int tid) {
    uint32_t base = smem_b + (uint32_t)slot * SLOT_BYTES;
    const char* shi = (const char*)&g_hhi[p][0][ck * 64];
    const char* slo = (const char*)&g_hlo[p][0][ck * 64];
    #pragma unroll
    for (int i = 0; i < 4; ++i) {
        int idx = i * NTHR + tid;             // 1024 16B pieces per plane
        int b = idx >> 3, j = idx & 7;
        uint32_t off = SWZ((uint32_t)(b * 128 + j * 16));
        cp16(base + off,          shi + (size_t)b * (HID * 2) + j * 16);
        cp16(base + 16384u + off, slo + (size_t)b * (HID * 2) + j * 16);
    }
}

// W slice (16 gate-rows x 512) -> fp16 hi + (lo*2048), padded rows.
__device__ __forceinline__ void load_W(const float* __restrict__ Whh, char* sm, int cta, int tid) {
    for (int idx = tid; idx < NG * HID; idx += NTHR) {
        int n = idx >> 9, k = idx & 511;
        int c = n >> 2, g = n & 3;
        int row = g * HID + cta * 4 + c;
        float w = Whh[(size_t)row * HID + k];
        __half whi = __float2half(w);
        __half wlo = __float2half((w - __half2float(whi)) * 2048.f);
        *(__half*)(sm + WHI_OFF + n * WROW + k * 2) = whi;
        *(__half*)(sm + WLO_OFF + n * WROW + k * 2) = wlo;
    }
}

__global__ void init_kernel() {
    size_t i = (size_t)blockIdx.x * blockDim.x + threadIdx.x;
    uint32_t* hh = (uint32_t*)&g_hhi[0][0][0];
    uint32_t* hl = (uint32_t*)&g_hlo[0][0][0];
    size_t n = 2ull * BATCH * HID / 2;
    for (size_t k = i; k < n; k += (size_t)gridDim.x * blockDim.x) { hh[k] = 0u; hl[k] = 0u; }
    if (i == 0) g_bar = 0u;
}

__global__ void __launch_bounds__(NTHR, 1)
fore_kernel(const float* __restrict__ src,
            const float* __restrict__ Wih_e, const float* __restrict__ Whh_e,
            const float* __restrict__ bih_e, const float* __restrict__ bhh_e,
            const float* __restrict__ Wih_d, const float* __restrict__ Whh_d,
            const float* __restrict__ bih_d, const float* __restrict__ bhh_d,
            const float* __restrict__ Wp,    const float* __restrict__ bp,
            const float* __restrict__ Wfc,   const float* __restrict__ bfc,
            float* __restrict__ out)
{
    extern __shared__ char sm[];
    const uint32_t smem_b = smem_u32_of(sm);
    float* Csm    = (float*)(sm + CSM_OFF);
    float* wih_sm = (float*)(sm + WIH_OFF);
    float* bsm    = (float*)(sm + BSM_OFF);
    float* wxa    = (float*)(sm + WXA_OFF);
    float* red    = (float*)(sm + RED_OFF);
    float* wfc_sm = (float*)(sm + WFC_OFF);

    const int tid  = threadIdx.x;
    const int cta  = blockIdx.x;
    const int wid  = tid >> 5;
    const int lane = tid & 31;
    const int kg   = wid >> 2;            // K group (0: K[0,256), 1: K[256,512))
    const int wm   = wid & 3;             // warp's M block (32 rows)
    const int eb   = tid >> 1;            // epilogue batch
    const int half = tid & 1;             // epilogue col half (2 cols)

    // ldmatrix lane addressing
    const int a_row  = (lane & 7) + ((lane >> 3) & 1) * 8;   // + m-base
    const int a_bcol = ((lane >> 4) & 1) * 16;
    const uint32_t b_off = (uint32_t)(((lane & 7) + ((lane >> 4) & 1) * 8) * WROW
                                      + ((lane >> 3) & 1) * 16);

    // ---- encoder weights ----
    load_W(Whh_e, sm, cta, tid);
    if (tid < NG * 8) {
        int n = tid >> 3, i = tid & 7;
        int c = n >> 2, g = n & 3;
        int row = g * HID + cta * 4 + c;
        wih_sm[n * 8 + i] = Wih_e[row * 8 + i];
    }
    if (tid < NG) {
        int c = tid >> 2, g = tid & 3;
        int row = g * HID + cta * 4 + c;
        bsm[tid] = bih_e[row] + bhh_e[row];
    }
    for (int k = tid; k < HID; k += NTHR) wfc_sm[k] = Wfc[k];
    __syncthreads();

    float cc[2] = {0.f, 0.f};
    unsigned target = 0;
    int p = 0;

    for (int step = 0; step < T_ENC + W_DEC; ++step) {
        const bool enc = (step < T_ENC);
        const int  t   = enc ? step : step - T_ENC;

        if (step == T_ENC) {                      // decoder weight swap
            load_W(Whh_d, sm, cta, tid);
            __syncthreads();
            if (tid < NG) {
                int c = tid >> 2, g = tid & 3;
                int row = g * HID + cta * 4 + c;
                float A = 0.f, B0 = 0.f;
                #pragma unroll
                for (int i = 0; i < 8; ++i) {
                    float wih = Wih_d[row * 8 + i];
                    A  += Wp[i] * wih;
                    B0 += bp[i] * wih;
                }
                bsm[tid] = bih_d[row] + bhh_d[row] + B0;
                wxa[tid] = A;
            }
            __syncthreads();
        }

        // =================== step GEMM ===================
        float accA[2][2][4], accB[2][2][4];
        #pragma unroll
        for (int i = 0; i < 2; ++i)
            #pragma unroll
            for (int j = 0; j < 2; ++j)
                #pragma unroll
                for (int q = 0; q < 4; ++q) { accA[i][j][q] = 0.f; accB[i][j][q] = 0.f; }

        stage_chunk(smem_b, 0, 0, p, tid);
        stage_chunk(smem_b, 2, 4, p, tid);
        cp_commit();

        #pragma unroll
        for (int i = 0; i < 4; ++i) {
            cp_wait<0>();
            __syncthreads();                      // chunks ready; prior slot reads done
            if (i < 3) {                          // prefetch next pair
                stage_chunk(smem_b, (i + 1) & 1,       i + 1, p, tid);
                stage_chunk(smem_b, 2 + ((i + 1) & 1), i + 5, p, tid);
                cp_commit();
            }
            const int ck = kg * 4 + i;
            const uint32_t sA  = smem_b + (uint32_t)(2 * kg + (i & 1)) * SLOT_BYTES;
            const uint32_t wB  = smem_b + (uint32_t)(ck * 128) + b_off;

            #pragma unroll
            for (int k16 = 0; k16 < 4; ++k16) {
                const int bc = a_bcol + k16 * 32;
                uint32_t Ah[2][4], Al[2][4], Bh[4], Bl[4];
                #pragma unroll
                for (int mt = 0; mt < 2; ++mt) {
                    uint32_t ra = sA + SWZ((uint32_t)((wm * 32 + mt * 16 + a_row) * 128 + bc));
                    ldsm4(Ah[mt][0], Ah[mt][1], Ah[mt][2], Ah[mt][3], ra);
                    ldsm4(Al[mt][0], Al[mt][1], Al[mt][2], Al[mt][3], ra + 16384u);
                }
                ldsm4(Bh[0], Bh[1], Bh[2], Bh[3], wB + WHI_OFF + k16 * 32);
                ldsm4(Bl[0], Bl[1], Bl[2], Bl[3], wB + WLO_OFF + k16 * 32);

                #pragma unroll
                for (int mt = 0; mt < 2; ++mt) {
                    #pragma unroll
                    for (int nt = 0; nt < 2; ++nt) {
                        uint32_t bh0 = Bh[nt * 2], bh1 = Bh[nt * 2 + 1];
                        uint32_t bl0 = Bl[nt * 2], bl1 = Bl[nt * 2 + 1];
                        mma16816(accA[mt][nt], Ah[mt][0], Ah[mt][1], Ah[mt][2], Ah[mt][3], bh0, bh1);
                        mma16816(accB[mt][nt], Al[mt][0], Al[mt][1], Al[mt][2], Al[mt][3], bh0, bh1);
                        mma16816(accB[mt][nt], Ah[mt][0], Ah[mt][1], Ah[mt][2], Ah[mt][3], bl0, bl1);
                    }
                }
            }
        }
        __syncthreads();                          // last slot reads done before C dump reuse

        // C reduction: group 0 stores, group 1 adds
        #pragma unroll
        for (int pass = 0; pass < 2; ++pass) {
            if (kg == pass) {
                #pragma unroll
                for (int mt = 0; mt < 2; ++mt) {
                    int r = wm * 32 + mt * 16 + (lane >> 2);
                    #pragma unroll
                    for (int nt = 0; nt < 2; ++nt) {
                        int cb = nt * 8 + (lane & 3) * 2;
                        float v0 = accA[mt][nt][0] + accB[mt][nt][0] * (1.f / 2048.f);
                        float v1 = accA[mt][nt][1] + accB[mt][nt][1] * (1.f / 2048.f);
                        float v2 = accA[mt][nt][2] + accB[mt][nt][2] * (1.f / 2048.f);
                        float v3 = accA[mt][nt][3] + accB[mt][nt][3] * (1.f / 2048.f);
                        if (pass == 0) {
                            Csm[r * 17 + cb]           = v0;
                            Csm[r * 17 + cb + 1]       = v1;
                            Csm[(r + 8) * 17 + cb]     = v2;
                            Csm[(r + 8) * 17 + cb + 1] = v3;
                        } else {
                            Csm[r * 17 + cb]           += v0;
                            Csm[r * 17 + cb + 1]       += v1;
                            Csm[(r + 8) * 17 + cb]     += v2;
                            Csm[(r + 8) * 17 + cb + 1] += v3;
                        }
                    }
                }
            }
            __syncthreads();
        }

        // =================== LSTM epilogue: thread = (batch, col-half) =========
        float xg8[8];
        float xv = 0.f;
        if (enc) {
            const float* sp = src + ((size_t)eb * T_ENC + t) * 8;
            float4 sa = *(const float4*)sp;
            float4 sb4 = *(const float4*)(sp + 4);
            xg8[0] = sa.x;  xg8[1] = sa.y;  xg8[2] = sa.z;  xg8[3] = sa.w;
            xg8[4] = sb4.x; xg8[5] = sb4.y; xg8[6] = sb4.z; xg8[7] = sb4.w;
        } else {
            xv = (t == 0) ? __ldg(&src[((size_t)eb * T_ENC + (T_ENC - 1)) * 8])
                          : ldcg(&g_pred[eb]);
        }

        uint32_t packh = 0, packl = 0;
        #pragma unroll
        for (int ci = 0; ci < 2; ++ci) {
            int nb = (half * 2 + ci) * 4;
            float gate[4];
            #pragma unroll
            for (int g = 0; g < 4; ++g) {
                int n = nb + g;
                float xpart;
                if (enc) {
                    const float* wr = wih_sm + n * 8;
                    xpart = xg8[0]*wr[0] + xg8[1]*wr[1] + xg8[2]*wr[2] + xg8[3]*wr[3]
                          + xg8[4]*wr[4] + xg8[5]*wr[5] + xg8[6]*wr[6] + xg8[7]*wr[7];
                } else {
                    xpart = xv * wxa[n];
                }
                gate[g] = Csm[eb * 17 + n] + xpart + bsm[n];
            }
            float ig = sigf(gate[0]), fg = sigf(gate[1]);
            float gg = tanh_acc(gate[2]), og = sigf(gate[3]);
            float cn = fg * cc[ci] + ig * gg;
            float hn = og * tanh_acc(cn);
            cc[ci] = cn;
            __half hh = __float2half(hn);
            __half hl = __float2half((hn - __half2float(hh)) * 2048.f);
            packh |= (uint32_t)__half_as_ushort(hh) << (ci * 16);
            packl |= (uint32_t)__half_as_ushort(hl) << (ci * 16);
        }
        stcg32(&g_hhi[p ^ 1][eb][cta * 4 + half * 2], packh);
        stcg32(&g_hlo[p ^ 1][eb][cta * 4 + half * 2], packl);

        gridbar(target);

        if (!enc) {
            // pred for batch == cta: sigmoid(h_new . Wfc + bfc)
            const __half* hr = &g_hhi[p ^ 1][cta][0];
            const __half* lr = &g_hlo[p ^ 1][cta][0];
            float part = 0.f;
            #pragma unroll
            for (int q = 0; q < 2; ++q) {
                int k = tid + q * NTHR;
                float hv = __half2float(__ushort_as_half(ldcg_h(hr + k)))
                         + __half2float(__ushort_as_half(ldcg_h(lr + k))) * (1.f / 2048.f);
                part = fmaf(hv, wfc_sm[k], part);
            }
            #pragma unroll
            for (int off = 16; off; off >>= 1)
                part += __shfl_down_sync(0xffffffffu, part, off);
            if (lane == 0) red[wid] = part;
            __syncthreads();
            if (tid == 0) {
                float s = 0.f;
                #pragma unroll
                for (int i = 0; i < 8; ++i) s += red[i];
                float pr = sigf(s + __ldg(bfc));
                stcg(&g_pred[cta], pr);
                out[cta * W_DEC + t] = pr;
            }
            gridbar(target);
        }
        p ^= 1;
    }
}

extern "C" void kernel_launch(void* const* d_in, const int* in_sizes, int n_in,
                              void* d_out, int out_size) {
    const float* src   = (const float*)d_in[0];
    const float* Wih_e = (const float*)d_in[1];
    const float* Whh_e = (const float*)d_in[2];
    const float* bih_e = (const float*)d_in[3];
    const float* bhh_e = (const float*)d_in[4];
    const float* Wih_d = (const float*)d_in[5];
    const float* Whh_d = (const float*)d_in[6];
    const float* bih_d = (const float*)d_in[7];
    const float* bhh_d = (const float*)d_in[8];
    const float* Wp    = (const float*)d_in[9];
    const float* bp    = (const float*)d_in[10];
    const float* Wfc   = (const float*)d_in[11];
    const float* bfc   = (const float*)d_in[12];
    float* out = (float*)d_out;

    cudaFuncSetAttribute(fore_kernel, cudaFuncAttributeMaxDynamicSharedMemorySize, SMEM_TOTAL);

    init_kernel<<<64, 256>>>();
    fore_kernel<<<NCTA, NTHR, SMEM_TOTAL>>>(src, Wih_e, Whh_e, bih_e, bhh_e,
                                            Wih_d, Whh_d, bih_d, bhh_d,
                                            Wp, bp, Wfc, bfc, out);
}